// round 17
// baseline (speedup 1.0000x reference)
#include <cuda_runtime.h>
#include <cstdint>

#define OUT_CH 16
#define PH 7
#define PW 7
#define SR 2
#define HH 80
#define WW 80
#define PLANE_ELEMS (HH * WW)            // 6400 floats
#define PLANE_BYTES (PLANE_ELEMS * 4)    // 25600 B
#define NPLANE (OUT_CH * PH * PW)        // 784 channels per batch
#define N_ROIS 512
#define NB 4
#define NPLANES_TOTAL (NB * NPLANE)      // 3136
#define GRID 148                          // 1 persistent block per SM
#define NSTG 6                            // pipeline stages
#define NCONS 512                         // consumer threads (16 warps)
#define TPB (NCONS + 32)                  // + 1 producer warp
#define SMEM_DYN (NSTG * PLANE_BYTES)     // 153600 B

// scratch (no allocation allowed)
__device__ __align__(16) float g_params[N_ROIS * 4];  // x1, y1, bh, bw
__device__ int g_perm[N_ROIS];            // rois sorted by batch
__device__ int g_boff[NB + 1];            // batch list offsets

__device__ __forceinline__ uint32_t smem_u32(const void* p) {
    uint32_t a;
    asm("{ .reg .u64 t; cvta.to.shared.u64 t, %1; cvt.u32.u64 %0, t; }"
        : "=r"(a) : "l"(p));
    return a;
}

__device__ __forceinline__ void mbar_wait(uint32_t mbar, uint32_t parity) {
    uint32_t done;
    asm volatile(
        "{\n\t.reg .pred p;\n\t"
        "mbarrier.try_wait.parity.acquire.cta.shared::cta.b64 p, [%1], %2;\n\t"
        "selp.b32 %0, 1, 0, p;\n\t}"
        : "=r"(done) : "r"(mbar), "r"(parity) : "memory");
    if (!done) {
        asm volatile(
            "{\n\t.reg .pred P1;\n\t"
            "WAIT_LOOP_%=:\n\t"
            "mbarrier.try_wait.parity.acquire.cta.shared::cta.b64 P1, [%0], %1, 0x989680;\n\t"
            "@P1 bra.uni WAIT_DONE_%=;\n\t"
            "bra.uni WAIT_LOOP_%=;\n\t"
            "WAIT_DONE_%=:\n\t}"
            :: "r"(mbar), "r"(parity) : "memory");
    }
}

// ── Kernel A: per-roi params + counting sort by batch ───────────────────
__global__ void __launch_bounds__(N_ROIS)
roi_prep_kernel(const float* __restrict__ rois) {
    __shared__ int s_cnt[NB];
    __shared__ int s_base[NB];
    const int t = threadIdx.x;
    if (t < NB) s_cnt[t] = 0;
    __syncthreads();

    const float* r = rois + (size_t)t * 5;
    const int   b  = (int)r[0];
    const float x1 = r[1] * (float)WW;
    const float y1 = r[2] * (float)HH;
    const float x2 = r[3] * (float)WW;
    const float y2 = r[4] * (float)HH;
    float* p = g_params + (size_t)t * 4;
    p[0] = x1;
    p[1] = y1;
    p[2] = fmaxf(y2 - y1, 0.1f) * (1.0f / (float)PH);
    p[3] = fmaxf(x2 - x1, 0.1f) * (1.0f / (float)PW);

    const int rank = atomicAdd(&s_cnt[b], 1);
    __syncthreads();
    if (t == 0) {
        int acc = 0;
        for (int i = 0; i < NB; i++) { s_base[i] = acc; g_boff[i] = acc; acc += s_cnt[i]; }
        g_boff[NB] = acc;
    }
    __syncthreads();
    g_perm[s_base[b] + rank] = t;
}

// ── Kernel B: warp-specialized producer/consumer streaming pipeline ─────
__global__ void __launch_bounds__(TPB)
psroi_align_kernel(const float* __restrict__ feat,
                   float* __restrict__ out) {
    extern __shared__ __align__(16) float s_buf[];      // [NSTG][PLANE_ELEMS]
    __shared__ alignas(8) uint64_t s_full[NSTG];
    __shared__ alignas(8) uint64_t s_empty[NSTG];

    const int tid = threadIdx.x;
    const int bid = blockIdx.x;
    const int nit = (NPLANES_TOTAL - bid + GRID - 1) / GRID;

    if (tid == 0) {
        #pragma unroll
        for (int j = 0; j < NSTG; j++) {
            asm volatile("mbarrier.init.shared.b64 [%0], 1;"
                         :: "r"(smem_u32(&s_full[j])) : "memory");
            asm volatile("mbarrier.init.shared.b64 [%0], %1;"
                         :: "r"(smem_u32(&s_empty[j])), "r"(NCONS / 32) : "memory");
        }
        asm volatile("fence.proxy.async.shared::cta;" ::: "memory");
    }
    __syncthreads();

    if (tid >= NCONS) {
        // ── producer warp: single thread streams planes into the ring ──
        if (tid == NCONS) {
            int s = 0, p = 1;                     // fresh barrier: parity-1 passes
            for (int i = 0; i < nit; i++) {
                const uint32_t emb = smem_u32(&s_empty[s]);
                const uint32_t fmb = smem_u32(&s_full[s]);
                mbar_wait(emb, p);
                const float* src = feat + (size_t)(bid + i * GRID) * PLANE_ELEMS;
                asm volatile("mbarrier.arrive.expect_tx.shared.b64 _, [%0], %1;"
                             :: "r"(fmb), "r"((uint32_t)PLANE_BYTES) : "memory");
                asm volatile(
                    "cp.async.bulk.shared::cta.global.mbarrier::complete_tx::bytes "
                    "[%0], [%1], %2, [%3];"
                    :: "r"(smem_u32(s_buf + s * PLANE_ELEMS)), "l"(src),
                       "r"((uint32_t)PLANE_BYTES), "r"(fmb)
                    : "memory");
                if (++s == NSTG) { s = 0; p ^= 1; }
            }
        }
        return;
    }

    // ── consumer warps ──────────────────────────────────────────────────
    int s = 0, p = 0;
    for (int i = 0; i < nit; i++) {
        const uint32_t fmb = smem_u32(&s_full[s]);
        const uint32_t emb = smem_u32(&s_empty[s]);
        mbar_wait(fmb, p);                        // acquire: TMA data visible

        const int plane = bid + i * GRID;
        const int b   = plane / NPLANE;
        const int idx = plane - b * NPLANE;       // channel = co*49 + ph*7 + pw
        const int rem = idx % (PH * PW);
        const int ph  = rem / PW;
        const int pw  = rem - ph * PW;
        const float* sp = s_buf + s * PLANE_ELEMS;

        const int off = g_boff[b];
        const int cnt = g_boff[b + 1] - off;
        const int nt  = cnt * 4;
        const int ntr = ((nt + NCONS - 1) / NCONS) * NCONS;   // full warps

        for (int t = tid; t < ntr; t += NCONS) {
            const int g = t >> 2;                 // roi within batch list
            const int smp = t & 3;                // sample point
            const bool valid = g < cnt;
            const int n = g_perm[off + (valid ? g : cnt - 1)];

            const float4 prm = *(const float4*)(g_params + (size_t)n * 4);
            const float x1 = prm.x, y1 = prm.y, bh = prm.z, bw = prm.w;

            const float fy = (smp & 2) ? 0.75f : 0.25f;
            const float fx = (smp & 1) ? 0.75f : 0.25f;
            const float y  = y1 + ((float)ph + fy) * bh;
            const float x  = x1 + ((float)pw + fx) * bw;

            // mask on UNCLIPPED coords (matches reference)
            const float m = (y >= -1.0f && y <= (float)HH &&
                             x >= -1.0f && x <= (float)WW) ? 1.0f : 0.0f;

            const float yc = fminf(fmaxf(y, 0.0f), (float)(HH - 1));
            const float xc = fminf(fmaxf(x, 0.0f), (float)(WW - 1));
            const int y0  = (int)yc;              // yc >= 0 -> floor == trunc
            const int x0  = (int)xc;
            const int y1i = min(y0 + 1, HH - 1);
            const int x1i = min(x0 + 1, WW - 1);
            const float ly = yc - (float)y0, lx = xc - (float)x0;
            const float hy = 1.0f - ly,      hx = 1.0f - lx;

            const float* r0 = sp + y0  * WW;
            const float* r1 = sp + y1i * WW;
            const float v00 = r0[x0];
            const float v01 = r0[x1i];
            const float v10 = r1[x0];
            const float v11 = r1[x1i];

            float v = m * (hy * (hx * v00 + lx * v01) + ly * (hx * v10 + lx * v11));

            // lanes smp=0..3 of one output are adjacent; whole warp active
            v += __shfl_xor_sync(0xffffffffu, v, 1);
            v += __shfl_xor_sync(0xffffffffu, v, 2);

            if (valid && smp == 0)
                out[(size_t)n * NPLANE + idx] = v * (1.0f / (SR * SR));
        }

        __syncwarp();                             // warp's smem reads consumed
        if ((tid & 31) == 0)
            asm volatile("mbarrier.arrive.shared.b64 _, [%0];"
                         :: "r"(emb) : "memory");
        if (++s == NSTG) { s = 0; p ^= 1; }
    }
}

extern "C" void kernel_launch(void* const* d_in, const int* in_sizes, int n_in,
                              void* d_out, int out_size) {
    const float* feat = (const float*)d_in[0];
    const float* rois = (const float*)d_in[1];
    float* out = (float*)d_out;
    cudaFuncSetAttribute(psroi_align_kernel,
                         cudaFuncAttributeMaxDynamicSharedMemorySize, SMEM_DYN);
    roi_prep_kernel<<<1, N_ROIS>>>(rois);
    psroi_align_kernel<<<GRID, TPB, SMEM_DYN>>>(feat, out);
}